// round 1
// baseline (speedup 1.0000x reference)
#include <cuda_runtime.h>
#include <cuda_bf16.h>
#include <math.h>

// Scratch (allocation-free): per-row partial |W| sums and integer sign-dots.
__device__ float g_wpart[1024];
__device__ int   g_dot[8 * 1024];

static __device__ __forceinline__ int sgn(float v) {
    return (v > 0.0f) - (v < 0.0f);
}

// One block per W row (o = blockIdx.x). 256 threads, each owns 4 contiguous
// columns (float4). Computes:
//   g_wpart[o] = sum_h |W[o,h]|
//   g_dot[b*1024+o] = sum_h sign(W[o,h]) * sign(x[b,h])   (exact int)
// x rows are the 8 first-token rows of hidden_states (32KB total -> L2 hot).
__global__ __launch_bounds__(256) void k_dot(const float* __restrict__ hidden,
                                             const float* __restrict__ W) {
    const int o = blockIdx.x;
    const int t = threadIdx.x;

    float4 w4 = reinterpret_cast<const float4*>(W + (size_t)o * 1024)[t];
    float asum = fabsf(w4.x) + fabsf(w4.y) + fabsf(w4.z) + fabsf(w4.w);

    const int sw0 = sgn(w4.x), sw1 = sgn(w4.y), sw2 = sgn(w4.z), sw3 = sgn(w4.w);

    int acc[8];
    #pragma unroll
    for (int bt = 0; bt < 8; bt++) {
        // first token of batch bt: hidden[bt, 0, :]
        const float4 x4 = reinterpret_cast<const float4*>(
            hidden + (size_t)bt * 4096 * 1024)[t];
        acc[bt] = sw0 * sgn(x4.x) + sw1 * sgn(x4.y)
                + sw2 * sgn(x4.z) + sw3 * sgn(x4.w);
    }

    // Warp reduction (deterministic)
    #pragma unroll
    for (int off = 16; off > 0; off >>= 1) {
        asum += __shfl_down_sync(0xFFFFFFFFu, asum, off);
        #pragma unroll
        for (int bt = 0; bt < 8; bt++)
            acc[bt] += __shfl_down_sync(0xFFFFFFFFu, acc[bt], off);
    }

    __shared__ float s_a[8];
    __shared__ int   s_d[8][8];   // [warp][batch]
    const int wid = t >> 5, lid = t & 31;
    if (lid == 0) {
        s_a[wid] = asum;
        #pragma unroll
        for (int bt = 0; bt < 8; bt++) s_d[wid][bt] = acc[bt];
    }
    __syncthreads();

    if (wid == 0) {
        float fa = (lid < 8) ? s_a[lid] : 0.0f;
        #pragma unroll
        for (int off = 4; off > 0; off >>= 1)
            fa += __shfl_down_sync(0xFFu, fa, off, 8);
        if (lid == 0) g_wpart[o] = fa;
    } else if (wid == 1) {
        // lanes 0..7 each own one batch: sum 8 warp partials
        if (lid < 8) {
            int s = 0;
            #pragma unroll
            for (int w = 0; w < 8; w++) s += s_d[w][lid];
            g_dot[lid * 1024 + o] = s;
        }
    }
}

// 8 blocks (one per batch) x 1024 threads. Deterministic tree-reduce of the
// 1024 row partials -> w_scale, then write tanh epilogue.
__global__ __launch_bounds__(1024) void k_epi(const float* __restrict__ bias,
                                              const float* __restrict__ alpha,
                                              float* __restrict__ out) {
    const int b = blockIdx.x;
    const int t = threadIdx.x;

    __shared__ float red[1024];
    red[t] = g_wpart[t];
    __syncthreads();
    #pragma unroll
    for (int s = 512; s > 0; s >>= 1) {
        if (t < s) red[t] += red[t + s];
        __syncthreads();
    }
    const float w_scale = red[0] * (1.0f / (1024.0f * 1024.0f));
    const float a = fmaxf(alpha[0], 1e-5f);

    const float v = a * w_scale * (float)g_dot[b * 1024 + t] + bias[t];
    out[b * 1024 + t] = tanhf(v);
}

extern "C" void kernel_launch(void* const* d_in, const int* in_sizes, int n_in,
                              void* d_out, int out_size) {
    const float* hidden = (const float*)d_in[0];  // (8, 4096, 1024) fp32
    const float* W      = (const float*)d_in[1];  // (1024, 1024)
    const float* bias   = (const float*)d_in[2];  // (1024,)
    const float* alpha  = (const float*)d_in[3];  // (1,)
    float* out = (float*)d_out;                   // (8, 1, 1024)

    k_dot<<<1024, 256>>>(hidden, W);
    k_epi<<<8, 1024>>>(bias, alpha, out);
}